// round 1
// baseline (speedup 1.0000x reference)
#include <cuda_runtime.h>
#include <math.h>
#include <stddef.h>

#define B_ 8
#define S_ 2048
#define M_ 256
#define D_ 512
#define P_ 512
#define H_ 8
#define SP1 (S_ + 1)          // 2049
#define SCALE 0.04419417382415922f   // 1/sqrt(512)

// ---------------- scratch (device globals; no allocations allowed) ----------
__device__ float g_ik[B_ * S_ * P_];          // 8 Mi floats
__device__ float g_iv[B_ * S_ * P_];
__device__ float g_mk[B_ * M_ * P_];
__device__ float g_mv[B_ * M_ * P_];
__device__ float g_q[B_ * H_ * M_ * P_];      // [b,h,m,p]
__device__ float g_scores[B_ * H_ * M_ * SP1];// [z, m, 0..2048] col0 = self
__device__ float g_concat[B_ * M_ * H_ * P_]; // [b, m, h, p]

// ---------------- generic NN GEMM:  C[M x N] = A[M x K] @ W[K x N] + bias ---
// 64x64 block tile, BK=16, 256 threads, 4x4 per thread. Grid covers M,N exactly.
__global__ __launch_bounds__(256) void gemm_nn_bias(
    const float* __restrict__ A, const float* __restrict__ W,
    const float* __restrict__ bias, float* __restrict__ C,
    int N, int K)
{
    __shared__ float As[16][66];   // As[k][m], pad->conflict-free transpose store
    __shared__ float Bs[16][64];   // Bs[k][n]
    const int tid = threadIdx.x;
    const int tx = tid & 15, ty = tid >> 4;
    const int m0 = blockIdx.y * 64, n0 = blockIdx.x * 64;
    const int aRow = tid >> 2, aCol = (tid & 3) << 2;
    const int bRow = tid >> 4, bCol = (tid & 15) << 2;
    const float* Ap = A + (size_t)(m0 + aRow) * K + aCol;
    const float* Bp = W + (size_t)bRow * N + n0 + bCol;
    float acc[4][4] = {};
    for (int k0 = 0; k0 < K; k0 += 16) {
        float4 av = *(const float4*)(Ap + k0);
        As[aCol + 0][aRow] = av.x; As[aCol + 1][aRow] = av.y;
        As[aCol + 2][aRow] = av.z; As[aCol + 3][aRow] = av.w;
        float4 bv = *(const float4*)(Bp + (size_t)k0 * N);
        *(float4*)&Bs[bRow][bCol] = bv;
        __syncthreads();
#pragma unroll
        for (int kk = 0; kk < 16; kk++) {
            float a0 = As[kk][ty * 4 + 0], a1 = As[kk][ty * 4 + 1];
            float a2 = As[kk][ty * 4 + 2], a3 = As[kk][ty * 4 + 3];
            float4 bb = *(const float4*)&Bs[kk][tx * 4];
            acc[0][0] += a0 * bb.x; acc[0][1] += a0 * bb.y; acc[0][2] += a0 * bb.z; acc[0][3] += a0 * bb.w;
            acc[1][0] += a1 * bb.x; acc[1][1] += a1 * bb.y; acc[1][2] += a1 * bb.z; acc[1][3] += a1 * bb.w;
            acc[2][0] += a2 * bb.x; acc[2][1] += a2 * bb.y; acc[2][2] += a2 * bb.z; acc[2][3] += a2 * bb.w;
            acc[3][0] += a3 * bb.x; acc[3][1] += a3 * bb.y; acc[3][2] += a3 * bb.z; acc[3][3] += a3 * bb.w;
        }
        __syncthreads();
    }
    float4 bia = *(const float4*)&bias[n0 + tx * 4];
#pragma unroll
    for (int i = 0; i < 4; i++) {
        int r = m0 + ty * 4 + i;
        float4 o;
        o.x = acc[i][0] + bia.x; o.y = acc[i][1] + bia.y;
        o.z = acc[i][2] + bia.z; o.w = acc[i][3] + bia.w;
        *(float4*)&C[(size_t)r * N + n0 + tx * 4] = o;
    }
}

// ---------------- Q projection: q[b,h,m,:] = mem[b,m,:] @ Wq[h] + bq[h] -----
__global__ __launch_bounds__(256) void gemm_q(
    const float* __restrict__ mem, const float* __restrict__ Wq,
    const float* __restrict__ bq, float* __restrict__ q)
{
    const int h = blockIdx.z;
    const float* W = Wq + (size_t)h * D_ * P_;
    const float* bias = bq + h * P_;
    __shared__ float As[16][66];
    __shared__ float Bs[16][64];
    const int tid = threadIdx.x;
    const int tx = tid & 15, ty = tid >> 4;
    const int m0 = blockIdx.y * 64, n0 = blockIdx.x * 64;
    const int aRow = tid >> 2, aCol = (tid & 3) << 2;
    const int bRow = tid >> 4, bCol = (tid & 15) << 2;
    const float* Ap = mem + (size_t)(m0 + aRow) * D_ + aCol;
    const float* Bp = W + (size_t)bRow * P_ + n0 + bCol;
    float acc[4][4] = {};
    for (int k0 = 0; k0 < D_; k0 += 16) {
        float4 av = *(const float4*)(Ap + k0);
        As[aCol + 0][aRow] = av.x; As[aCol + 1][aRow] = av.y;
        As[aCol + 2][aRow] = av.z; As[aCol + 3][aRow] = av.w;
        float4 bv = *(const float4*)(Bp + (size_t)k0 * P_);
        *(float4*)&Bs[bRow][bCol] = bv;
        __syncthreads();
#pragma unroll
        for (int kk = 0; kk < 16; kk++) {
            float a0 = As[kk][ty * 4 + 0], a1 = As[kk][ty * 4 + 1];
            float a2 = As[kk][ty * 4 + 2], a3 = As[kk][ty * 4 + 3];
            float4 bb = *(const float4*)&Bs[kk][tx * 4];
            acc[0][0] += a0 * bb.x; acc[0][1] += a0 * bb.y; acc[0][2] += a0 * bb.z; acc[0][3] += a0 * bb.w;
            acc[1][0] += a1 * bb.x; acc[1][1] += a1 * bb.y; acc[1][2] += a1 * bb.z; acc[1][3] += a1 * bb.w;
            acc[2][0] += a2 * bb.x; acc[2][1] += a2 * bb.y; acc[2][2] += a2 * bb.z; acc[2][3] += a2 * bb.w;
            acc[3][0] += a3 * bb.x; acc[3][1] += a3 * bb.y; acc[3][2] += a3 * bb.z; acc[3][3] += a3 * bb.w;
        }
        __syncthreads();
    }
    float4 bia = *(const float4*)&bias[n0 + tx * 4];
#pragma unroll
    for (int i = 0; i < 4; i++) {
        int r = m0 + ty * 4 + i;          // 0..2047
        int b = r >> 8, m = r & 255;
        float4 o;
        o.x = acc[i][0] + bia.x; o.y = acc[i][1] + bia.y;
        o.z = acc[i][2] + bia.z; o.w = acc[i][3] + bia.w;
        size_t off = ((size_t)(b * H_ + h) * M_ + m) * P_ + n0 + tx * 4;
        *(float4*)&q[off] = o;
    }
}

// ---------------- scores (NT): sc[z,m,1+s] = (q[z,m,:] . ik[b,s,:]) * SCALE -
__global__ __launch_bounds__(256) void gemm_scores(
    const float* __restrict__ q, const float* __restrict__ ik,
    float* __restrict__ sc)
{
    const int z = blockIdx.z, b = z >> 3;
    const float* A = q + (size_t)z * M_ * P_;
    const float* Bt = ik + (size_t)b * S_ * P_;
    __shared__ float As[16][66];
    __shared__ float Bs[16][66];
    const int tid = threadIdx.x;
    const int tx = tid & 15, ty = tid >> 4;
    const int m0 = blockIdx.y * 64, n0 = blockIdx.x * 64;
    const int aRow = tid >> 2, aCol = (tid & 3) << 2;
    const float* Ap = A + (size_t)(m0 + aRow) * P_ + aCol;
    const float* Bp = Bt + (size_t)(n0 + aRow) * P_ + aCol;
    float acc[4][4] = {};
    for (int k0 = 0; k0 < P_; k0 += 16) {
        float4 av = *(const float4*)(Ap + k0);
        As[aCol + 0][aRow] = av.x; As[aCol + 1][aRow] = av.y;
        As[aCol + 2][aRow] = av.z; As[aCol + 3][aRow] = av.w;
        float4 bv = *(const float4*)(Bp + k0);
        Bs[aCol + 0][aRow] = bv.x; Bs[aCol + 1][aRow] = bv.y;
        Bs[aCol + 2][aRow] = bv.z; Bs[aCol + 3][aRow] = bv.w;
        __syncthreads();
#pragma unroll
        for (int kk = 0; kk < 16; kk++) {
            float a0 = As[kk][ty * 4 + 0], a1 = As[kk][ty * 4 + 1];
            float a2 = As[kk][ty * 4 + 2], a3 = As[kk][ty * 4 + 3];
            float b0 = Bs[kk][tx * 4 + 0], b1 = Bs[kk][tx * 4 + 1];
            float b2 = Bs[kk][tx * 4 + 2], b3 = Bs[kk][tx * 4 + 3];
            acc[0][0] += a0 * b0; acc[0][1] += a0 * b1; acc[0][2] += a0 * b2; acc[0][3] += a0 * b3;
            acc[1][0] += a1 * b0; acc[1][1] += a1 * b1; acc[1][2] += a1 * b2; acc[1][3] += a1 * b3;
            acc[2][0] += a2 * b0; acc[2][1] += a2 * b1; acc[2][2] += a2 * b2; acc[2][3] += a2 * b3;
            acc[3][0] += a3 * b0; acc[3][1] += a3 * b1; acc[3][2] += a3 * b2; acc[3][3] += a3 * b3;
        }
        __syncthreads();
    }
#pragma unroll
    for (int i = 0; i < 4; i++) {
        int m = m0 + ty * 4 + i;
        size_t base = (size_t)z * M_ * SP1 + (size_t)m * SP1 + 1 + n0 + tx * 4;
#pragma unroll
        for (int j = 0; j < 4; j++) sc[base + j] = acc[i][j] * SCALE;
    }
}

// ---------------- self score: sc[z,m,0] = (q[z,m,:] . mk[b,m,:]) * SCALE ----
__global__ __launch_bounds__(256) void self_score(
    const float* __restrict__ q, const float* __restrict__ mk,
    float* __restrict__ sc)
{
    int gw = (blockIdx.x * 256 + threadIdx.x) >> 5;   // global warp id
    int lane = threadIdx.x & 31;
    int z = gw >> 8, m = gw & 255, b = z >> 3;
    const float* qp = q + ((size_t)z * M_ + m) * P_;
    const float* kp = mk + ((size_t)b * M_ + m) * P_;
    float s = 0.f;
    for (int i = lane * 4; i < P_; i += 32 * 4) {
        float4 qa = *(const float4*)(qp + i);
        float4 ka = *(const float4*)(kp + i);
        s += qa.x * ka.x + qa.y * ka.y + qa.z * ka.z + qa.w * ka.w;
    }
    for (int o = 16; o; o >>= 1) s += __shfl_xor_sync(0xffffffffu, s, o);
    if (lane == 0)
        sc[(size_t)z * M_ * SP1 + (size_t)m * SP1] = s * SCALE;
}

// ---------------- softmax over 2049 per row, in place -----------------------
__global__ __launch_bounds__(256) void softmax_rows(float* __restrict__ sc)
{
    float* p = sc + (size_t)blockIdx.x * SP1;
    const int tid = threadIdx.x;
    const int lane = tid & 31, wid = tid >> 5;
    __shared__ float redm[8], reds[8];
    float v[9];
    int cnt = 0;
    float vmax = -1e30f;
    for (int i = tid; i < SP1; i += 256) { v[cnt] = p[i]; vmax = fmaxf(vmax, v[cnt]); cnt++; }
    for (int o = 16; o; o >>= 1) vmax = fmaxf(vmax, __shfl_xor_sync(0xffffffffu, vmax, o));
    if (lane == 0) redm[wid] = vmax;
    __syncthreads();
    if (tid == 0) {
        float t = redm[0];
        for (int i = 1; i < 8; i++) t = fmaxf(t, redm[i]);
        redm[0] = t;
    }
    __syncthreads();
    vmax = redm[0];
    float s = 0.f;
    for (int i = 0; i < cnt; i++) { v[i] = __expf(v[i] - vmax); s += v[i]; }
    for (int o = 16; o; o >>= 1) s += __shfl_xor_sync(0xffffffffu, s, o);
    if (lane == 0) reds[wid] = s;
    __syncthreads();
    if (tid == 0) {
        float t = 0.f;
        for (int i = 0; i < 8; i++) t += reds[i];
        reds[0] = t;
    }
    __syncthreads();
    float inv = 1.0f / reds[0];
    cnt = 0;
    for (int i = tid; i < SP1; i += 256) { p[i] = v[cnt] * inv; cnt++; }
}

// ---- val (NN, lda=2049): concat[b,m,h,:] = attn[z,m,1:] @ iv[b] + attn0*mv -
__global__ __launch_bounds__(256) void gemm_val(
    const float* __restrict__ sc, const float* __restrict__ iv,
    const float* __restrict__ mv, float* __restrict__ concat)
{
    const int z = blockIdx.z, b = z >> 3, h = z & 7;
    const float* A = sc + (size_t)z * M_ * SP1 + 1;   // lda = 2049 (unaligned)
    const float* Bm = iv + (size_t)b * S_ * P_;
    __shared__ float As[16][66];
    __shared__ float Bs[16][64];
    const int tid = threadIdx.x;
    const int tx = tid & 15, ty = tid >> 4;
    const int m0 = blockIdx.y * 64, n0 = blockIdx.x * 64;
    const int aRow = tid >> 2, aCol = (tid & 3) << 2;
    const int bRow = tid >> 4, bCol = (tid & 15) << 2;
    const float* Ap = A + (size_t)(m0 + aRow) * SP1 + aCol;
    const float* Bp = Bm + (size_t)bRow * P_ + n0 + bCol;
    float acc[4][4] = {};
    for (int k0 = 0; k0 < S_; k0 += 16) {
        As[aCol + 0][aRow] = Ap[k0 + 0];
        As[aCol + 1][aRow] = Ap[k0 + 1];
        As[aCol + 2][aRow] = Ap[k0 + 2];
        As[aCol + 3][aRow] = Ap[k0 + 3];
        float4 bv = *(const float4*)(Bp + (size_t)k0 * P_);
        *(float4*)&Bs[bRow][bCol] = bv;
        __syncthreads();
#pragma unroll
        for (int kk = 0; kk < 16; kk++) {
            float a0 = As[kk][ty * 4 + 0], a1 = As[kk][ty * 4 + 1];
            float a2 = As[kk][ty * 4 + 2], a3 = As[kk][ty * 4 + 3];
            float4 bb = *(const float4*)&Bs[kk][tx * 4];
            acc[0][0] += a0 * bb.x; acc[0][1] += a0 * bb.y; acc[0][2] += a0 * bb.z; acc[0][3] += a0 * bb.w;
            acc[1][0] += a1 * bb.x; acc[1][1] += a1 * bb.y; acc[1][2] += a1 * bb.z; acc[1][3] += a1 * bb.w;
            acc[2][0] += a2 * bb.x; acc[2][1] += a2 * bb.y; acc[2][2] += a2 * bb.z; acc[2][3] += a2 * bb.w;
            acc[3][0] += a3 * bb.x; acc[3][1] += a3 * bb.y; acc[3][2] += a3 * bb.z; acc[3][3] += a3 * bb.w;
        }
        __syncthreads();
    }
#pragma unroll
    for (int i = 0; i < 4; i++) {
        int m = m0 + ty * 4 + i;                       // 0..255
        float selfw = sc[(size_t)z * M_ * SP1 + (size_t)m * SP1];
        float4 mvv = *(const float4*)&mv[((size_t)b * M_ + m) * P_ + n0 + tx * 4];
        float4 o;
        o.x = acc[i][0] + selfw * mvv.x;
        o.y = acc[i][1] + selfw * mvv.y;
        o.z = acc[i][2] + selfw * mvv.z;
        o.w = acc[i][3] + selfw * mvv.w;
        size_t off = ((size_t)(b * M_ + m)) * (H_ * P_) + (size_t)h * P_ + n0 + tx * 4;
        *(float4*)&concat[off] = o;
    }
}

// ---------------- launch ----------------------------------------------------
extern "C" void kernel_launch(void* const* d_in, const int* in_sizes, int n_in,
                              void* d_out, int out_size)
{
    const float* input_seq    = (const float*)d_in[0];
    const float* memory_cells = (const float*)d_in[1];
    const float* Wk = (const float*)d_in[2];
    const float* bk = (const float*)d_in[3];
    const float* Wv = (const float*)d_in[4];
    const float* bv = (const float*)d_in[5];
    const float* Wq = (const float*)d_in[6];
    const float* bq = (const float*)d_in[7];
    const float* Wo = (const float*)d_in[8];
    const float* bo = (const float*)d_in[9];
    float* out = (float*)d_out;

    float *p_ik, *p_iv, *p_mk, *p_mv, *p_q, *p_sc, *p_cc;
    cudaGetSymbolAddress((void**)&p_ik, g_ik);
    cudaGetSymbolAddress((void**)&p_iv, g_iv);
    cudaGetSymbolAddress((void**)&p_mk, g_mk);
    cudaGetSymbolAddress((void**)&p_mv, g_mv);
    cudaGetSymbolAddress((void**)&p_q,  g_q);
    cudaGetSymbolAddress((void**)&p_sc, g_scores);
    cudaGetSymbolAddress((void**)&p_cc, g_concat);

    dim3 blk(256);
    // projections
    gemm_nn_bias<<<dim3(P_ / 64, (B_ * S_) / 64), blk>>>(input_seq, Wk, bk, p_ik, P_, D_);
    gemm_nn_bias<<<dim3(P_ / 64, (B_ * S_) / 64), blk>>>(input_seq, Wv, bv, p_iv, P_, D_);
    gemm_nn_bias<<<dim3(P_ / 64, (B_ * M_) / 64), blk>>>(memory_cells, Wk, bk, p_mk, P_, D_);
    gemm_nn_bias<<<dim3(P_ / 64, (B_ * M_) / 64), blk>>>(memory_cells, Wv, bv, p_mv, P_, D_);
    gemm_q<<<dim3(P_ / 64, (B_ * M_) / 64, H_), blk>>>(memory_cells, Wq, bq, p_q);
    // attention
    gemm_scores<<<dim3(S_ / 64, M_ / 64, B_ * H_), blk>>>(p_q, p_ik, p_sc);
    self_score<<<(B_ * H_ * M_) / 8, blk>>>(p_q, p_mk, p_sc);
    softmax_rows<<<B_ * H_ * M_, blk>>>(p_sc);
    gemm_val<<<dim3(P_ / 64, M_ / 64, B_ * H_), blk>>>(p_sc, p_iv, p_mv, p_cc);
    // output projection
    gemm_nn_bias<<<dim3(P_ / 64, (B_ * M_) / 64), blk>>>(p_cc, Wo, bo, out, P_, H_ * P_);
}

// round 2
// speedup vs baseline: 2.1868x; 2.1868x over previous
#include <cuda_runtime.h>
#include <stdint.h>
#include <stddef.h>

#define B_ 8
#define S_ 2048
#define M_ 256
#define D_ 512
#define P_ 512
#define H_ 8
#define SP1 (S_ + 1)          // 2049
#define SCALE 0.04419417382415922f   // 1/sqrt(512)

// ---------------- scratch (device globals; no allocations allowed) ----------
__device__ float g_ik[B_ * S_ * P_];
__device__ float g_iv[B_ * S_ * P_];
__device__ float g_mk[B_ * M_ * P_];
__device__ float g_mv[B_ * M_ * P_];
__device__ float g_q[B_ * H_ * M_ * P_];      // [b,h,m,p]
__device__ float g_scores[B_ * H_ * M_ * SP1];// [z,m,0..2048] col0 = self
__device__ float g_concat[B_ * M_ * H_ * P_]; // [b,m,h,p]

// ---------------- helpers ----------------------------------------------------
__device__ __forceinline__ uint32_t f2tf(float x) {
    uint32_t r; asm("cvt.rna.tf32.f32 %0, %1;" : "=r"(r) : "f"(x)); return r;
}
__device__ __forceinline__ void mma8(float* d, uint32_t a0, uint32_t a1,
                                     uint32_t a2, uint32_t a3,
                                     uint32_t b0, uint32_t b1) {
    asm volatile(
        "mma.sync.aligned.m16n8k8.row.col.f32.tf32.tf32.f32 "
        "{%0,%1,%2,%3},{%4,%5,%6,%7},{%8,%9},{%0,%1,%2,%3};"
        : "+f"(d[0]), "+f"(d[1]), "+f"(d[2]), "+f"(d[3])
        : "r"(a0), "r"(a1), "r"(a2), "r"(a3), "r"(b0), "r"(b1));
}

// SMEM layouts (permuted-k):
//  A/NT-B tile: [row 0..127][pk 0..15], pk=(k&3)*4+(k>>2); float4 quad tg of a
//  row yields k = {tg, tg+4, tg+8, tg+12}  -> both k-steps of m16n8k8.
//  NN-B tile:   [pk 0..15][n 0..127] stride 132.

// aligned A fill (lda multiple of 4)
__device__ __forceinline__ void fillA(uint32_t* As, const float* A, int lda, int k0) {
    int fr = threadIdx.x >> 2, fc = threadIdx.x & 3;
#pragma unroll
    for (int rr = 0; rr < 2; rr++) {
        int row = fr + rr * 64;
        float4 v = *(const float4*)(A + (size_t)row * lda + k0 + fc * 4);
        uint32_t* d = As + row * 16 + fc;
        d[0] = f2tf(v.x); d[4] = f2tf(v.y); d[8] = f2tf(v.z); d[12] = f2tf(v.w);
    }
}
// unaligned A fill (scalar loads; for attn rows with lda=2049)
__device__ __forceinline__ void fillA_s(uint32_t* As, const float* A, int lda, int k0) {
    int fr = threadIdx.x >> 2, fc = threadIdx.x & 3;
#pragma unroll
    for (int rr = 0; rr < 2; rr++) {
        int row = fr + rr * 64;
        const float* p = A + (size_t)row * lda + k0 + fc * 4;
        uint32_t* d = As + row * 16 + fc;
        d[0] = f2tf(p[0]); d[4] = f2tf(p[1]); d[8] = f2tf(p[2]); d[12] = f2tf(p[3]);
    }
}
// NN B fill: gmem B[K x N] row-major -> Bs[pk][n] (stride 132)
__device__ __forceinline__ void fillB_nn(uint32_t* Bs, const float* Bg, int ldb,
                                         int k0, int n0) {
    int bk = threadIdx.x >> 5, bq = threadIdx.x & 31;
#pragma unroll
    for (int rr = 0; rr < 2; rr++) {
        int k = bk + rr * 8;
        float4 v = *(const float4*)(Bg + (size_t)(k0 + k) * ldb + n0 + bq * 4);
        int pk = ((k & 3) << 2) | (k >> 2);
        uint32_t* d = Bs + pk * 132 + bq * 4;
        d[0] = f2tf(v.x); d[1] = f2tf(v.y); d[2] = f2tf(v.z); d[3] = f2tf(v.w);
    }
}

// compute one BK=16 chunk; Bs in NT layout ([n][pk])
__device__ __forceinline__ void compute_nt(const uint32_t* As, const uint32_t* Bs,
                                           float acc[4][4][4], int g, int tg,
                                           int wm, int wn) {
    uint4 al[4], ah[4], bb[4];
#pragma unroll
    for (int mt = 0; mt < 4; mt++) {
        int row = wm * 64 + mt * 16;
        al[mt] = *(const uint4*)(As + (row + g) * 16 + tg * 4);
        ah[mt] = *(const uint4*)(As + (row + 8 + g) * 16 + tg * 4);
    }
#pragma unroll
    for (int nt = 0; nt < 4; nt++)
        bb[nt] = *(const uint4*)(Bs + (wn * 32 + nt * 8 + g) * 16 + tg * 4);
#pragma unroll
    for (int mt = 0; mt < 4; mt++)
#pragma unroll
        for (int nt = 0; nt < 4; nt++) {
            mma8(acc[mt][nt], al[mt].x, ah[mt].x, al[mt].y, ah[mt].y, bb[nt].x, bb[nt].y);
            mma8(acc[mt][nt], al[mt].z, ah[mt].z, al[mt].w, ah[mt].w, bb[nt].z, bb[nt].w);
        }
}
// compute one BK=16 chunk; Bs in NN layout ([pk][n] stride 132)
__device__ __forceinline__ void compute_nn(const uint32_t* As, const uint32_t* Bs,
                                           float acc[4][4][4], int g, int tg,
                                           int wm, int wn) {
    uint4 al[4], ah[4];
    uint32_t bf[4][4];
#pragma unroll
    for (int mt = 0; mt < 4; mt++) {
        int row = wm * 64 + mt * 16;
        al[mt] = *(const uint4*)(As + (row + g) * 16 + tg * 4);
        ah[mt] = *(const uint4*)(As + (row + 8 + g) * 16 + tg * 4);
    }
#pragma unroll
    for (int nt = 0; nt < 4; nt++) {
        int nn = wn * 32 + nt * 8 + g;
        bf[nt][0] = Bs[(4 * tg + 0) * 132 + nn];
        bf[nt][1] = Bs[(4 * tg + 1) * 132 + nn];
        bf[nt][2] = Bs[(4 * tg + 2) * 132 + nn];
        bf[nt][3] = Bs[(4 * tg + 3) * 132 + nn];
    }
#pragma unroll
    for (int mt = 0; mt < 4; mt++)
#pragma unroll
        for (int nt = 0; nt < 4; nt++) {
            mma8(acc[mt][nt], al[mt].x, ah[mt].x, al[mt].y, ah[mt].y, bf[nt][0], bf[nt][1]);
            mma8(acc[mt][nt], al[mt].z, ah[mt].z, al[mt].w, ah[mt].w, bf[nt][2], bf[nt][3]);
        }
}

// ---------------- NN GEMM with bias: C[Mr x N] = A @ Bg + bias --------------
__global__ __launch_bounds__(256) void k_gemm_nn(
    const float* __restrict__ A, const float* __restrict__ Bg,
    const float* __restrict__ bias, float* __restrict__ C, int N, int K)
{
    __shared__ uint32_t As[128 * 16];
    __shared__ uint32_t Bs[16 * 132];
    const int tid = threadIdx.x;
    const int lane = tid & 31, wid = tid >> 5;
    const int g = lane >> 2, tg = lane & 3;
    const int wm = wid & 1, wn = wid >> 1;
    const int m0 = blockIdx.y * 128, n0 = blockIdx.x * 128;
    float acc[4][4][4] = {};
    for (int k0 = 0; k0 < K; k0 += 16) {
        fillA(As, A + (size_t)m0 * K, K, k0);
        fillB_nn(Bs, Bg, N, k0, n0);
        __syncthreads();
        compute_nn(As, Bs, acc, g, tg, wm, wn);
        __syncthreads();
    }
#pragma unroll
    for (int mt = 0; mt < 4; mt++)
#pragma unroll
        for (int nt = 0; nt < 4; nt++) {
            int row = m0 + wm * 64 + mt * 16 + g;
            int col = n0 + wn * 32 + nt * 8 + 2 * tg;
            float2 bi = *(const float2*)(bias + col);
            float2 o0 = {acc[mt][nt][0] + bi.x, acc[mt][nt][1] + bi.y};
            float2 o1 = {acc[mt][nt][2] + bi.x, acc[mt][nt][3] + bi.y};
            *(float2*)(C + (size_t)row * N + col) = o0;
            *(float2*)(C + (size_t)(row + 8) * N + col) = o1;
        }
}

// ---------------- Q projection: q[b,h,m,:] = mem @ Wq[h] + bq[h] ------------
__global__ __launch_bounds__(256) void k_gemm_q(
    const float* __restrict__ mem, const float* __restrict__ Wq,
    const float* __restrict__ bq, float* __restrict__ q)
{
    __shared__ uint32_t As[128 * 16];
    __shared__ uint32_t Bs[16 * 132];
    const int h = blockIdx.z;
    const float* W = Wq + (size_t)h * D_ * P_;
    const float* bias = bq + h * P_;
    const int tid = threadIdx.x;
    const int lane = tid & 31, wid = tid >> 5;
    const int g = lane >> 2, tg = lane & 3;
    const int wm = wid & 1, wn = wid >> 1;
    const int m0 = blockIdx.y * 128, n0 = blockIdx.x * 128;
    float acc[4][4][4] = {};
    for (int k0 = 0; k0 < D_; k0 += 16) {
        fillA(As, mem + (size_t)m0 * D_, D_, k0);
        fillB_nn(Bs, W, P_, k0, n0);
        __syncthreads();
        compute_nn(As, Bs, acc, g, tg, wm, wn);
        __syncthreads();
    }
#pragma unroll
    for (int mt = 0; mt < 4; mt++)
#pragma unroll
        for (int nt = 0; nt < 4; nt++) {
            int row = m0 + wm * 64 + mt * 16 + g;
            int col = n0 + wn * 32 + nt * 8 + 2 * tg;
            float2 bi = *(const float2*)(bias + col);
#pragma unroll
            for (int rr = 0; rr < 2; rr++) {
                int r = row + rr * 8;
                int b = r >> 8, m = r & 255;
                float2 o = {acc[mt][nt][2 * rr + 0] + bi.x,
                            acc[mt][nt][2 * rr + 1] + bi.y};
                *(float2*)(q + ((size_t)(b * H_ + h) * M_ + m) * P_ + col) = o;
            }
        }
}

// ---------------- scores (NT): sc[z,m,1+s] = (q[z,m,:].ik[b,s,:])*SCALE -----
__global__ __launch_bounds__(256) void k_scores(
    const float* __restrict__ q, const float* __restrict__ ik,
    float* __restrict__ sc)
{
    __shared__ uint32_t As[128 * 16];
    __shared__ uint32_t Bs[128 * 16];
    const int z = blockIdx.z, b = z >> 3;
    const float* A = q + (size_t)z * M_ * P_;
    const float* Bt = ik + (size_t)b * S_ * P_;
    const int tid = threadIdx.x;
    const int lane = tid & 31, wid = tid >> 5;
    const int g = lane >> 2, tg = lane & 3;
    const int wm = wid & 1, wn = wid >> 1;
    const int m0 = blockIdx.y * 128, n0 = blockIdx.x * 128;
    float acc[4][4][4] = {};
    for (int k0 = 0; k0 < P_; k0 += 16) {
        fillA(As, A + (size_t)m0 * P_, P_, k0);
        fillA(Bs, Bt + (size_t)n0 * P_, P_, k0);   // NT: B rows are K-major too
        __syncthreads();
        compute_nt(As, Bs, acc, g, tg, wm, wn);
        __syncthreads();
    }
#pragma unroll
    for (int mt = 0; mt < 4; mt++)
#pragma unroll
        for (int nt = 0; nt < 4; nt++) {
            int m = m0 + wm * 64 + mt * 16 + g;
            int s = n0 + wn * 32 + nt * 8 + 2 * tg;
            size_t base = (size_t)z * M_ * SP1 + (size_t)m * SP1 + 1 + s;
            sc[base]               = acc[mt][nt][0] * SCALE;
            sc[base + 1]           = acc[mt][nt][1] * SCALE;
            sc[base + 8 * SP1]     = acc[mt][nt][2] * SCALE;
            sc[base + 8 * SP1 + 1] = acc[mt][nt][3] * SCALE;
        }
}

// ---------------- self score: sc[z,m,0] = (q[z,m,:].mk[b,m,:])*SCALE --------
__global__ __launch_bounds__(256) void self_score(
    const float* __restrict__ q, const float* __restrict__ mk,
    float* __restrict__ sc)
{
    int gw = (blockIdx.x * 256 + threadIdx.x) >> 5;
    int lane = threadIdx.x & 31;
    int z = gw >> 8, m = gw & 255, b = z >> 3;
    const float* qp = q + ((size_t)z * M_ + m) * P_;
    const float* kp = mk + ((size_t)b * M_ + m) * P_;
    float s = 0.f;
    for (int i = lane * 4; i < P_; i += 128) {
        float4 qa = *(const float4*)(qp + i);
        float4 ka = *(const float4*)(kp + i);
        s += qa.x * ka.x + qa.y * ka.y + qa.z * ka.z + qa.w * ka.w;
    }
    for (int o = 16; o; o >>= 1) s += __shfl_xor_sync(0xffffffffu, s, o);
    if (lane == 0)
        sc[(size_t)z * M_ * SP1 + (size_t)m * SP1] = s * SCALE;
}

// ---------------- softmax over 2049 per row, in place -----------------------
__global__ __launch_bounds__(256) void softmax_rows(float* __restrict__ sc)
{
    float* p = sc + (size_t)blockIdx.x * SP1;
    const int tid = threadIdx.x;
    const int lane = tid & 31, wid = tid >> 5;
    __shared__ float redm[8], reds[8];
    float v[9];
    int cnt = 0;
    float vmax = -1e30f;
    for (int i = tid; i < SP1; i += 256) { v[cnt] = p[i]; vmax = fmaxf(vmax, v[cnt]); cnt++; }
    for (int o = 16; o; o >>= 1) vmax = fmaxf(vmax, __shfl_xor_sync(0xffffffffu, vmax, o));
    if (lane == 0) redm[wid] = vmax;
    __syncthreads();
    if (tid == 0) {
        float t = redm[0];
        for (int i = 1; i < 8; i++) t = fmaxf(t, redm[i]);
        redm[0] = t;
    }
    __syncthreads();
    vmax = redm[0];
    float s = 0.f;
    for (int i = 0; i < cnt; i++) { v[i] = __expf(v[i] - vmax); s += v[i]; }
    for (int o = 16; o; o >>= 1) s += __shfl_xor_sync(0xffffffffu, s, o);
    if (lane == 0) reds[wid] = s;
    __syncthreads();
    if (tid == 0) {
        float t = 0.f;
        for (int i = 0; i < 8; i++) t += reds[i];
        reds[0] = t;
    }
    __syncthreads();
    float inv = 1.0f / reds[0];
    cnt = 0;
    for (int i = tid; i < SP1; i += 256) { p[i] = v[cnt] * inv; cnt++; }
}

// ---- val (NN): concat[b,m,h,:] = attn[z,m,1:] @ iv[b] + attn0*mv -----------
__global__ __launch_bounds__(256) void k_val(
    const float* __restrict__ sc, const float* __restrict__ iv,
    const float* __restrict__ mv, float* __restrict__ concat)
{
    __shared__ uint32_t As[128 * 16];
    __shared__ uint32_t Bs[16 * 132];
    const int z = blockIdx.z, b = z >> 3, h = z & 7;
    const float* scbase = sc + (size_t)z * M_ * SP1;
    const float* A = scbase + 1;                   // lda = 2049, unaligned
    const float* Bm = iv + (size_t)b * S_ * P_;
    const int tid = threadIdx.x;
    const int lane = tid & 31, wid = tid >> 5;
    const int g = lane >> 2, tg = lane & 3;
    const int wm = wid & 1, wn = wid >> 1;
    const int m0 = blockIdx.y * 128, n0 = blockIdx.x * 128;
    float acc[4][4][4] = {};
    for (int k0 = 0; k0 < S_; k0 += 16) {
        fillA_s(As, A + (size_t)m0 * SP1, SP1, k0);
        fillB_nn(Bs, Bm, P_, k0, n0);
        __syncthreads();
        compute_nn(As, Bs, acc, g, tg, wm, wn);
        __syncthreads();
    }
#pragma unroll
    for (int mt = 0; mt < 4; mt++)
#pragma unroll
        for (int nt = 0; nt < 4; nt++) {
            int m = m0 + wm * 64 + mt * 16 + g;
            int col = n0 + wn * 32 + nt * 8 + 2 * tg;
#pragma unroll
            for (int rr = 0; rr < 2; rr++) {
                int mm = m + rr * 8;
                float sw = scbase[(size_t)mm * SP1];
                float2 mvv = *(const float2*)(mv + ((size_t)(b * M_ + mm)) * P_ + col);
                float2 o = {acc[mt][nt][2 * rr + 0] + sw * mvv.x,
                            acc[mt][nt][2 * rr + 1] + sw * mvv.y};
                *(float2*)(concat + ((size_t)(b * M_ + mm)) * (H_ * P_) +
                           (size_t)h * P_ + col) = o;
            }
        }
}

// ---------------- launch ----------------------------------------------------
extern "C" void kernel_launch(void* const* d_in, const int* in_sizes, int n_in,
                              void* d_out, int out_size)
{
    const float* input_seq    = (const float*)d_in[0];
    const float* memory_cells = (const float*)d_in[1];
    const float* Wk = (const float*)d_in[2];
    const float* bk = (const float*)d_in[3];
    const float* Wv = (const float*)d_in[4];
    const float* bv = (const float*)d_in[5];
    const float* Wq = (const float*)d_in[6];
    const float* bq = (const float*)d_in[7];
    const float* Wo = (const float*)d_in[8];
    const float* bo = (const float*)d_in[9];
    float* out = (float*)d_out;

    float *p_ik, *p_iv, *p_mk, *p_mv, *p_q, *p_sc, *p_cc;
    cudaGetSymbolAddress((void**)&p_ik, g_ik);
    cudaGetSymbolAddress((void**)&p_iv, g_iv);
    cudaGetSymbolAddress((void**)&p_mk, g_mk);
    cudaGetSymbolAddress((void**)&p_mv, g_mv);
    cudaGetSymbolAddress((void**)&p_q,  g_q);
    cudaGetSymbolAddress((void**)&p_sc, g_scores);
    cudaGetSymbolAddress((void**)&p_cc, g_concat);

    dim3 blk(256);
    k_gemm_nn<<<dim3(P_ / 128, (B_ * S_) / 128), blk>>>(input_seq, Wk, bk, p_ik, P_, D_);
    k_gemm_nn<<<dim3(P_ / 128, (B_ * S_) / 128), blk>>>(input_seq, Wv, bv, p_iv, P_, D_);
    k_gemm_nn<<<dim3(P_ / 128, (B_ * M_) / 128), blk>>>(memory_cells, Wk, bk, p_mk, P_, D_);
    k_gemm_nn<<<dim3(P_ / 128, (B_ * M_) / 128), blk>>>(memory_cells, Wv, bv, p_mv, P_, D_);
    k_gemm_q<<<dim3(P_ / 128, (B_ * M_) / 128, H_), blk>>>(memory_cells, Wq, bq, p_q);

    k_scores<<<dim3(S_ / 128, M_ / 128, B_ * H_), blk>>>(p_q, p_ik, p_sc);
    self_score<<<(B_ * H_ * M_) / 8, blk>>>(p_q, p_mk, p_sc);
    softmax_rows<<<B_ * H_ * M_, blk>>>(p_sc);
    k_val<<<dim3(P_ / 128, M_ / 128, B_ * H_), blk>>>(p_sc, p_iv, p_mv, p_cc);

    k_gemm_nn<<<dim3(P_ / 128, (B_ * M_) / 128), blk>>>(p_cc, Wo, bo, out, P_, H_ * P_);
}

// round 3
// speedup vs baseline: 3.3804x; 1.5458x over previous
#include <cuda_runtime.h>
#include <stdint.h>
#include <stddef.h>

#define B_ 8
#define S_ 2048
#define M_ 256
#define D_ 512
#define P_ 512
#define H_ 8
#define SCALE 0.04419417382415922f   // 1/sqrt(512)

// ---------------- scratch (device globals) ----------------------------------
__device__ float g_ik[B_ * S_ * P_];            // rounded tf32 values
__device__ float g_ivT[B_ * P_ * S_];           // transposed, rounded
__device__ float g_mk[B_ * M_ * P_];            // fp32
__device__ float g_mv[B_ * M_ * P_];            // fp32
__device__ float g_q[B_ * H_ * M_ * P_];        // rounded
__device__ float g_probs[(size_t)B_ * H_ * M_ * S_]; // aligned, rounded post-softmax
__device__ float g_self[B_ * H_ * M_];
__device__ float g_concat[B_ * M_ * H_ * P_];   // rounded
__device__ float g_WkT[P_ * D_];
__device__ float g_WvT[P_ * D_];
__device__ float g_WqT[H_ * P_ * D_];
__device__ float g_WoT[P_ * H_ * P_];

// ---------------- helpers ----------------------------------------------------
__device__ __forceinline__ float rtf(float x) {
    uint32_t r; asm("cvt.rna.tf32.f32 %0, %1;" : "=r"(r) : "f"(x));
    return __uint_as_float(r);
}
__device__ __forceinline__ void mma8(float* d, float a0, float a1, float a2,
                                     float a3, float b0, float b1) {
    asm volatile(
        "mma.sync.aligned.m16n8k8.row.col.f32.tf32.tf32.f32 "
        "{%0,%1,%2,%3},{%4,%5,%6,%7},{%8,%9},{%0,%1,%2,%3};"
        : "+f"(d[0]), "+f"(d[1]), "+f"(d[2]), "+f"(d[3])
        : "r"(__float_as_uint(a0)), "r"(__float_as_uint(a1)),
          "r"(__float_as_uint(a2)), "r"(__float_as_uint(a3)),
          "r"(__float_as_uint(b0)), "r"(__float_as_uint(b1)));
}
__device__ __forceinline__ void cpa16(uint32_t s, const float* g) {
    asm volatile("cp.async.cg.shared.global [%0], [%1], 16;\n" ::"r"(s), "l"(g));
}
#define CPA_COMMIT() asm volatile("cp.async.commit_group;\n" ::: "memory")
#define CPA_WAIT1()  asm volatile("cp.async.wait_group 1;\n" ::: "memory")

// ---------------- weight transpose + round: out[n*K+k] = rtf(in[k*N+n]) -----
__global__ void k_transpose(const float* __restrict__ in, float* __restrict__ out,
                            int K, int N) {
    __shared__ float t[32][33];
    size_t zoff = (size_t)blockIdx.z * K * N;
    int k0 = blockIdx.y * 32, n0 = blockIdx.x * 32;
    int x = threadIdx.x, y = threadIdx.y;   // 32 x 8
#pragma unroll
    for (int i = 0; i < 32; i += 8)
        t[y + i][x] = in[zoff + (size_t)(k0 + y + i) * N + n0 + x];
    __syncthreads();
#pragma unroll
    for (int i = 0; i < 32; i += 8)
        out[zoff + (size_t)(n0 + y + i) * K + k0 + x] = rtf(t[x][y + i]);
}

// ---------------- pipelined NT GEMM (128x128 tile, BK=16, 3 stages) ---------
// A rows k-major (lda), B rows k-major (ldb). 256 thr, 8 warps (2x4), 64x32/warp.
__device__ __forceinline__ void stage_load(float* As, float* Bs,
                                           const float* Ag, const float* Bg,
                                           int lda, int ldb, int k0, int tid) {
    int row = tid >> 1, qb = (tid & 1) * 2;
    const float* ga = Ag + (size_t)row * lda + k0 + qb * 4;
    uint32_t sa = (uint32_t)__cvta_generic_to_shared(As + row * 16 + qb * 4);
    cpa16(sa, ga); cpa16(sa + 16, ga + 4);
    const float* gb = Bg + (size_t)row * ldb + k0 + qb * 4;
    uint32_t sb = (uint32_t)__cvta_generic_to_shared(Bs + row * 16 + qb * 4);
    cpa16(sb, gb); cpa16(sb + 16, gb + 4);
}

template <bool CVTA>
__device__ __forceinline__ void compute_stage(const float* As, const float* Bs,
                                              float acc[4][4][4], int g, int tg,
                                              int wm, int wn) {
    float4 al[4], ah[4], bb[4];
#pragma unroll
    for (int mt = 0; mt < 4; mt++) {
        int row = wm * 64 + mt * 16;
        al[mt] = *(const float4*)(As + (row + g) * 16 + tg * 4);
        ah[mt] = *(const float4*)(As + (row + 8 + g) * 16 + tg * 4);
        if (CVTA) {
            al[mt].x = rtf(al[mt].x); al[mt].y = rtf(al[mt].y);
            al[mt].z = rtf(al[mt].z); al[mt].w = rtf(al[mt].w);
            ah[mt].x = rtf(ah[mt].x); ah[mt].y = rtf(ah[mt].y);
            ah[mt].z = rtf(ah[mt].z); ah[mt].w = rtf(ah[mt].w);
        }
    }
#pragma unroll
    for (int nt = 0; nt < 4; nt++)
        bb[nt] = *(const float4*)(Bs + (wn * 32 + nt * 8 + g) * 16 + tg * 4);
#pragma unroll
    for (int mt = 0; mt < 4; mt++)
#pragma unroll
        for (int nt = 0; nt < 4; nt++) {
            mma8(acc[mt][nt], al[mt].x, ah[mt].x, al[mt].y, ah[mt].y,
                 bb[nt].x, bb[nt].y);
            mma8(acc[mt][nt], al[mt].z, ah[mt].z, al[mt].w, ah[mt].w,
                 bb[nt].z, bb[nt].w);
        }
}

// MODE 0: A=mem(2048 rows);   z=0->mk(C0,+bk), z=1->mv(C1,+bv), z>=2->q(C2,+bq[h], round, scatter)
// MODE 1: A=input(16384 rows);z=0->ik(C0,+bk,round), z=1->ivT(C1,+bv,round,transposed)
// MODE 2: scores: A=q[z], B=ik[b]; C0=probs, *SCALE
// MODE 3: val: A=probs[z], B=ivT[b]; C0=concat, +self*mv, round
// MODE 4: final: A=concat, B=WoT; C0=out, +bo
template <int MODE>
__global__ __launch_bounds__(256) void gemm_nt(
    const float* __restrict__ A0,
    const float* __restrict__ B0, const float* __restrict__ B1,
    const float* __restrict__ B2,
    const float* __restrict__ bias0, const float* __restrict__ bias1,
    const float* __restrict__ bias2,
    float* __restrict__ C0, float* __restrict__ C1, float* __restrict__ C2,
    const float* __restrict__ selfw, const float* __restrict__ mvp,
    int K)
{
    __shared__ __align__(16) float As[3][128 * 16];
    __shared__ __align__(16) float Bs[3][128 * 16];
    const int tid = threadIdx.x;
    const int lane = tid & 31, wid = tid >> 5;
    const int g = lane >> 2, tg = lane & 3;
    const int wm = wid & 1, wn = wid >> 1;
    const int m0 = blockIdx.y * 128, n0 = blockIdx.x * 128;
    const int z = blockIdx.z;

    const float *Ag, *Bg;
    int lda, ldb;
    if (MODE == 0) {
        lda = D_; ldb = D_;
        Ag = A0 + (size_t)m0 * lda;
        const float* Bb = (z == 0) ? B0 : (z == 1) ? B1
                          : (B2 + (size_t)(z - 2) * P_ * D_);
        Bg = Bb + (size_t)n0 * ldb;
    } else if (MODE == 1) {
        lda = D_; ldb = D_;
        Ag = A0 + (size_t)m0 * lda;
        Bg = ((z == 0) ? B0 : B1) + (size_t)n0 * ldb;
    } else if (MODE == 2) {
        lda = P_; ldb = P_;
        Ag = A0 + (size_t)z * M_ * P_ + (size_t)m0 * lda;
        Bg = B0 + (size_t)(z >> 3) * S_ * P_ + (size_t)n0 * ldb;
    } else if (MODE == 3) {
        lda = S_; ldb = S_;
        Ag = A0 + (size_t)z * M_ * S_ + (size_t)m0 * lda;
        Bg = B0 + (size_t)(z >> 3) * P_ * S_ + (size_t)n0 * ldb;
    } else {
        lda = H_ * P_; ldb = H_ * P_;
        Ag = A0 + (size_t)m0 * lda;
        Bg = B0 + (size_t)n0 * ldb;
    }
    const bool CVTA = (MODE <= 1);

    float acc[4][4][4] = {};
    stage_load(As[0], Bs[0], Ag, Bg, lda, ldb, 0, tid);  CPA_COMMIT();
    stage_load(As[1], Bs[1], Ag, Bg, lda, ldb, 16, tid); CPA_COMMIT();
    const int NK = K / 16;
    for (int i = 0; i < NK; i++) {
        CPA_WAIT1();
        __syncthreads();
        int pf = i + 2;
        if (pf < NK)
            stage_load(As[pf % 3], Bs[pf % 3], Ag, Bg, lda, ldb, pf * 16, tid);
        CPA_COMMIT();
        if (CVTA) compute_stage<true >(As[i % 3], Bs[i % 3], acc, g, tg, wm, wn);
        else      compute_stage<false>(As[i % 3], Bs[i % 3], acc, g, tg, wm, wn);
        __syncthreads();
    }

#pragma unroll
    for (int mt = 0; mt < 4; mt++)
#pragma unroll
        for (int nt = 0; nt < 4; nt++) {
            int col = n0 + wn * 32 + nt * 8 + 2 * tg;
#pragma unroll
            for (int rr = 0; rr < 2; rr++) {
                int R = m0 + wm * 64 + mt * 16 + g + rr * 8;
                float v0 = acc[mt][nt][2 * rr + 0];
                float v1 = acc[mt][nt][2 * rr + 1];
                if (MODE == 0) {
                    if (z == 0) {
                        float2 bi = *(const float2*)(bias0 + col);
                        *(float2*)&C0[(size_t)R * P_ + col] =
                            make_float2(v0 + bi.x, v1 + bi.y);
                    } else if (z == 1) {
                        float2 bi = *(const float2*)(bias1 + col);
                        *(float2*)&C1[(size_t)R * P_ + col] =
                            make_float2(v0 + bi.x, v1 + bi.y);
                    } else {
                        int h = z - 2;
                        float2 bi = *(const float2*)(bias2 + h * P_ + col);
                        int b = R >> 8, m = R & 255;
                        *(float2*)&C2[(((size_t)(b * H_ + h)) * M_ + m) * P_ + col] =
                            make_float2(rtf(v0 + bi.x), rtf(v1 + bi.y));
                    }
                } else if (MODE == 1) {
                    if (z == 0) {
                        float2 bi = *(const float2*)(bias0 + col);
                        *(float2*)&C0[(size_t)R * P_ + col] =
                            make_float2(rtf(v0 + bi.x), rtf(v1 + bi.y));
                    } else {
                        float2 bi = *(const float2*)(bias1 + col);
                        int b = R >> 11, s = R & 2047;
                        C1[((size_t)b * P_ + col) * S_ + s]     = rtf(v0 + bi.x);
                        C1[((size_t)b * P_ + col + 1) * S_ + s] = rtf(v1 + bi.y);
                    }
                } else if (MODE == 2) {
                    *(float2*)&C0[((size_t)z * M_ + R) * S_ + col] =
                        make_float2(v0 * SCALE, v1 * SCALE);
                } else if (MODE == 3) {
                    int b = z >> 3, h = z & 7;
                    float sw = selfw[(size_t)z * M_ + R];
                    float2 mvv = *(const float2*)(mvp + ((size_t)(b * M_ + R)) * P_ + col);
                    *(float2*)&C0[(size_t)(b * M_ + R) * (H_ * P_) + h * P_ + col] =
                        make_float2(rtf(v0 + sw * mvv.x), rtf(v1 + sw * mvv.y));
                } else {
                    float2 bi = *(const float2*)(bias0 + col);
                    *(float2*)&C0[(size_t)R * P_ + col] =
                        make_float2(v0 + bi.x, v1 + bi.y);
                }
            }
        }
}

// ---------------- self score -> g_self ---------------------------------------
__global__ __launch_bounds__(256) void self_score(
    const float* __restrict__ q, const float* __restrict__ mk,
    float* __restrict__ selfo)
{
    int gw = (blockIdx.x * 256 + threadIdx.x) >> 5;
    int lane = threadIdx.x & 31;
    int z = gw >> 8, m = gw & 255, b = z >> 3;
    const float* qp = q + ((size_t)z * M_ + m) * P_;
    const float* kp = mk + ((size_t)b * M_ + m) * P_;
    float s = 0.f;
    for (int i = lane * 4; i < P_; i += 128) {
        float4 qa = *(const float4*)(qp + i);
        float4 ka = *(const float4*)(kp + i);
        s += qa.x * ka.x + qa.y * ka.y + qa.z * ka.z + qa.w * ka.w;
    }
    for (int o = 16; o; o >>= 1) s += __shfl_xor_sync(0xffffffffu, s, o);
    if (lane == 0) selfo[(size_t)z * M_ + m] = s * SCALE;
}

// ---------------- softmax over [self, 2048 probs]; writes rounded probs -----
__global__ __launch_bounds__(256) void softmax_rows(
    float* __restrict__ probs, float* __restrict__ selfv)
{
    float* p = probs + (size_t)blockIdx.x * S_;
    const int tid = threadIdx.x;
    const int lane = tid & 31, wid = tid >> 5;
    __shared__ float red[8];
    float sv = selfv[blockIdx.x];
    float v[8];
    float vmax = sv;
#pragma unroll
    for (int i = 0; i < 8; i++) { v[i] = p[tid + i * 256]; vmax = fmaxf(vmax, v[i]); }
    for (int o = 16; o; o >>= 1) vmax = fmaxf(vmax, __shfl_xor_sync(0xffffffffu, vmax, o));
    if (lane == 0) red[wid] = vmax;
    __syncthreads();
    if (tid == 0) {
        float t = red[0];
        for (int i = 1; i < 8; i++) t = fmaxf(t, red[i]);
        red[0] = t;
    }
    __syncthreads();
    vmax = red[0];
    float s = 0.f;
#pragma unroll
    for (int i = 0; i < 8; i++) { v[i] = __expf(v[i] - vmax); s += v[i]; }
    float es = __expf(sv - vmax);
    if (tid == 0) s += es;
    for (int o = 16; o; o >>= 1) s += __shfl_xor_sync(0xffffffffu, s, o);
    if (lane == 0) red[wid] = s;
    __syncthreads();
    if (tid == 0) {
        float t = 0.f;
        for (int i = 0; i < 8; i++) t += red[i];
        red[0] = t;
    }
    __syncthreads();
    float inv = 1.0f / red[0];
#pragma unroll
    for (int i = 0; i < 8; i++) p[tid + i * 256] = rtf(v[i] * inv);
    if (tid == 0) selfv[blockIdx.x] = es * inv;
}

// ---------------- launch ----------------------------------------------------
extern "C" void kernel_launch(void* const* d_in, const int* in_sizes, int n_in,
                              void* d_out, int out_size)
{
    const float* input_seq    = (const float*)d_in[0];
    const float* memory_cells = (const float*)d_in[1];
    const float* Wk = (const float*)d_in[2];
    const float* bk = (const float*)d_in[3];
    const float* Wv = (const float*)d_in[4];
    const float* bv = (const float*)d_in[5];
    const float* Wq = (const float*)d_in[6];
    const float* bq = (const float*)d_in[7];
    const float* Wo = (const float*)d_in[8];
    const float* bo = (const float*)d_in[9];
    float* out = (float*)d_out;

    float *p_ik, *p_ivT, *p_mk, *p_mv, *p_q, *p_pr, *p_sf, *p_cc;
    float *p_WkT, *p_WvT, *p_WqT, *p_WoT;
    cudaGetSymbolAddress((void**)&p_ik,  g_ik);
    cudaGetSymbolAddress((void**)&p_ivT, g_ivT);
    cudaGetSymbolAddress((void**)&p_mk,  g_mk);
    cudaGetSymbolAddress((void**)&p_mv,  g_mv);
    cudaGetSymbolAddress((void**)&p_q,   g_q);
    cudaGetSymbolAddress((void**)&p_pr,  g_probs);
    cudaGetSymbolAddress((void**)&p_sf,  g_self);
    cudaGetSymbolAddress((void**)&p_cc,  g_concat);
    cudaGetSymbolAddress((void**)&p_WkT, g_WkT);
    cudaGetSymbolAddress((void**)&p_WvT, g_WvT);
    cudaGetSymbolAddress((void**)&p_WqT, g_WqT);
    cudaGetSymbolAddress((void**)&p_WoT, g_WoT);

    dim3 tb(32, 8);
    k_transpose<<<dim3(16, 16), tb>>>(Wk, p_WkT, D_, P_);
    k_transpose<<<dim3(16, 16), tb>>>(Wv, p_WvT, D_, P_);
    k_transpose<<<dim3(16, 16, H_), tb>>>(Wq, p_WqT, D_, P_);
    k_transpose<<<dim3(16, 128), tb>>>(Wo, p_WoT, H_ * P_, P_);

    // mem-side: mk, mv, q (fused)
    gemm_nt<0><<<dim3(4, 16, 10), 256>>>(memory_cells, p_WkT, p_WvT, p_WqT,
                                         bk, bv, bq, p_mk, p_mv, p_q,
                                         nullptr, nullptr, D_);
    // input-side: ik, ivT (fused)
    gemm_nt<1><<<dim3(4, 128, 2), 256>>>(input_seq, p_WkT, p_WvT, nullptr,
                                         bk, bv, nullptr, p_ik, p_ivT, nullptr,
                                         nullptr, nullptr, D_);
    // scores
    gemm_nt<2><<<dim3(16, 2, 64), 256>>>(p_q, p_ik, nullptr, nullptr,
                                         nullptr, nullptr, nullptr,
                                         p_pr, nullptr, nullptr,
                                         nullptr, nullptr, P_);
    self_score<<<2048, 256>>>(p_q, p_mk, p_sf);
    softmax_rows<<<B_ * H_ * M_, 256>>>(p_pr, p_sf);
    // attn @ V  (+ self path)
    gemm_nt<3><<<dim3(4, 2, 64), 256>>>(p_pr, p_ivT, nullptr, nullptr,
                                        nullptr, nullptr, nullptr,
                                        p_cc, nullptr, nullptr,
                                        p_sf, p_mv, S_);
    // output projection
    gemm_nt<4><<<dim3(4, 16, 1), 256>>>(p_cc, p_WoT, nullptr, nullptr,
                                        bo, nullptr, nullptr,
                                        out, nullptr, nullptr,
                                        nullptr, nullptr, H_ * P_);
}

// round 4
// speedup vs baseline: 3.4874x; 1.0316x over previous
#include <cuda_runtime.h>
#include <stdint.h>
#include <stddef.h>

#define B_ 8
#define S_ 2048
#define M_ 256
#define D_ 512
#define P_ 512
#define H_ 8
#define SCALE 0.04419417382415922f   // 1/sqrt(512)

// ---------------- scratch (device globals) ----------------------------------
__device__ float g_ik[B_ * S_ * P_];            // rounded tf32 values
__device__ float g_ivT[B_ * P_ * S_];           // transposed, rounded
__device__ float g_mk[B_ * M_ * P_];            // fp32
__device__ float g_mv[B_ * M_ * P_];            // fp32
__device__ float g_q[B_ * H_ * M_ * P_];        // rounded
__device__ float g_probs[(size_t)B_ * H_ * M_ * S_]; // aligned, rounded post-softmax
__device__ float g_self[B_ * H_ * M_];
__device__ float g_concat[B_ * M_ * H_ * P_];   // rounded
__device__ float g_WkT[P_ * D_];
__device__ float g_WvT[P_ * D_];
__device__ float g_WqT[H_ * P_ * D_];
__device__ float g_WoT[P_ * H_ * P_];

// ---------------- helpers ----------------------------------------------------
__device__ __forceinline__ float rtf(float x) {
    uint32_t r; asm("cvt.rna.tf32.f32 %0, %1;" : "=r"(r) : "f"(x));
    return __uint_as_float(r);
}
__device__ __forceinline__ void mma8(float* d, float a0, float a1, float a2,
                                     float a3, float b0, float b1) {
    asm volatile(
        "mma.sync.aligned.m16n8k8.row.col.f32.tf32.tf32.f32 "
        "{%0,%1,%2,%3},{%4,%5,%6,%7},{%8,%9},{%0,%1,%2,%3};"
        : "+f"(d[0]), "+f"(d[1]), "+f"(d[2]), "+f"(d[3])
        : "r"(__float_as_uint(a0)), "r"(__float_as_uint(a1)),
          "r"(__float_as_uint(a2)), "r"(__float_as_uint(a3)),
          "r"(__float_as_uint(b0)), "r"(__float_as_uint(b1)));
}
__device__ __forceinline__ void cpa16(uint32_t s, const float* g) {
    asm volatile("cp.async.cg.shared.global [%0], [%1], 16;\n" ::"r"(s), "l"(g));
}
#define CPA_COMMIT() asm volatile("cp.async.commit_group;\n" ::: "memory")
#define CPA_WAIT1()  asm volatile("cp.async.wait_group 1;\n" ::: "memory")

// ---------------- weight transpose + round: out[n*K+k] = rtf(in[k*N+n]) -----
__global__ void k_transpose(const float* __restrict__ in, float* __restrict__ out,
                            int K, int N) {
    __shared__ float t[32][33];
    size_t zoff = (size_t)blockIdx.z * K * N;
    int k0 = blockIdx.y * 32, n0 = blockIdx.x * 32;
    int x = threadIdx.x, y = threadIdx.y;   // 32 x 8
#pragma unroll
    for (int i = 0; i < 32; i += 8)
        t[y + i][x] = in[zoff + (size_t)(k0 + y + i) * N + n0 + x];
    __syncthreads();
#pragma unroll
    for (int i = 0; i < 32; i += 8)
        out[zoff + (size_t)(n0 + y + i) * K + k0 + x] = rtf(t[x][y + i]);
}

// ---------------- pipelined NT GEMM (128x128 tile, BK=16, 3 stages) ---------
__device__ __forceinline__ void stage_load(float* As, float* Bs,
                                           const float* Ag, const float* Bg,
                                           int lda, int ldb, int k0, int tid) {
    int row = tid >> 1, qb = (tid & 1) * 2;
    const float* ga = Ag + (size_t)row * lda + k0 + qb * 4;
    uint32_t sa = (uint32_t)__cvta_generic_to_shared(As + row * 16 + qb * 4);
    cpa16(sa, ga); cpa16(sa + 16, ga + 4);
    const float* gb = Bg + (size_t)row * ldb + k0 + qb * 4;
    uint32_t sb = (uint32_t)__cvta_generic_to_shared(Bs + row * 16 + qb * 4);
    cpa16(sb, gb); cpa16(sb + 16, gb + 4);
}

template <bool CVTA>
__device__ __forceinline__ void compute_stage(const float* As, const float* Bs,
                                              float acc[4][4][4], int g, int tg,
                                              int wm, int wn) {
    float4 al[4], ah[4], bb[4];
#pragma unroll
    for (int mt = 0; mt < 4; mt++) {
        int row = wm * 64 + mt * 16;
        al[mt] = *(const float4*)(As + (row + g) * 16 + tg * 4);
        ah[mt] = *(const float4*)(As + (row + 8 + g) * 16 + tg * 4);
        if (CVTA) {
            al[mt].x = rtf(al[mt].x); al[mt].y = rtf(al[mt].y);
            al[mt].z = rtf(al[mt].z); al[mt].w = rtf(al[mt].w);
            ah[mt].x = rtf(ah[mt].x); ah[mt].y = rtf(ah[mt].y);
            ah[mt].z = rtf(ah[mt].z); ah[mt].w = rtf(ah[mt].w);
        }
    }
#pragma unroll
    for (int nt = 0; nt < 4; nt++)
        bb[nt] = *(const float4*)(Bs + (wn * 32 + nt * 8 + g) * 16 + tg * 4);
#pragma unroll
    for (int mt = 0; mt < 4; mt++)
#pragma unroll
        for (int nt = 0; nt < 4; nt++) {
            mma8(acc[mt][nt], al[mt].x, ah[mt].x, al[mt].y, ah[mt].y,
                 bb[nt].x, bb[nt].y);
            mma8(acc[mt][nt], al[mt].z, ah[mt].z, al[mt].w, ah[mt].w,
                 bb[nt].z, bb[nt].w);
        }
}

// MODE 0: A=mem(2048 rows);   z=0->mk(+bk), z=1->mv(+bv), z>=2->q(+bq[h], round, scatter)
// MODE 1: A=input(16384 rows);z=0->ik(+bk,round), z=1->ivT(+bv,round,transposed)
// MODE 2: scores: A=q[z], B=ik[b]; probs, *SCALE
// MODE 3: val: A=probs[z], B=ivT[b]; concat, +self*mv, round
// MODE 4: final: A=concat, B=WoT; out, +bo
template <int MODE, int K>
__global__ __launch_bounds__(256, 2) void gemm_nt(
    const float* __restrict__ A0,
    const float* __restrict__ B0, const float* __restrict__ B1,
    const float* __restrict__ B2,
    const float* __restrict__ bias0, const float* __restrict__ bias1,
    const float* __restrict__ bias2,
    float* __restrict__ C0, float* __restrict__ C1, float* __restrict__ C2,
    const float* __restrict__ selfw, const float* __restrict__ mvp)
{
    __shared__ __align__(16) float As[3][128 * 16];
    __shared__ __align__(16) float Bs[3][128 * 16];
    const int tid = threadIdx.x;
    const int lane = tid & 31, wid = tid >> 5;
    const int g = lane >> 2, tg = lane & 3;
    const int wm = wid & 1, wn = wid >> 1;
    const int m0 = blockIdx.y * 128, n0 = blockIdx.x * 128;
    const int z = blockIdx.z;

    const float *Ag, *Bg;
    int lda, ldb;
    if (MODE == 0) {
        lda = D_; ldb = D_;
        Ag = A0 + (size_t)m0 * lda;
        const float* Bb = (z == 0) ? B0 : (z == 1) ? B1
                          : (B2 + (size_t)(z - 2) * P_ * D_);
        Bg = Bb + (size_t)n0 * ldb;
    } else if (MODE == 1) {
        lda = D_; ldb = D_;
        Ag = A0 + (size_t)m0 * lda;
        Bg = ((z == 0) ? B0 : B1) + (size_t)n0 * ldb;
    } else if (MODE == 2) {
        lda = P_; ldb = P_;
        Ag = A0 + (size_t)z * M_ * P_ + (size_t)m0 * lda;
        Bg = B0 + (size_t)(z >> 3) * S_ * P_ + (size_t)n0 * ldb;
    } else if (MODE == 3) {
        lda = S_; ldb = S_;
        Ag = A0 + (size_t)z * M_ * S_ + (size_t)m0 * lda;
        Bg = B0 + (size_t)(z >> 3) * P_ * S_ + (size_t)n0 * ldb;
    } else {
        lda = H_ * P_; ldb = H_ * P_;
        Ag = A0 + (size_t)m0 * lda;
        Bg = B0 + (size_t)n0 * ldb;
    }
    const bool CVTA = (MODE <= 1);

    float acc[4][4][4] = {};
    stage_load(As[0], Bs[0], Ag, Bg, lda, ldb, 0, tid);  CPA_COMMIT();
    stage_load(As[1], Bs[1], Ag, Bg, lda, ldb, 16, tid); CPA_COMMIT();
    constexpr int NK = K / 16;
#pragma unroll 2
    for (int i = 0; i < NK; i++) {
        CPA_WAIT1();
        __syncthreads();
        int pf = i + 2;
        if (pf < NK)
            stage_load(As[pf % 3], Bs[pf % 3], Ag, Bg, lda, ldb, pf * 16, tid);
        CPA_COMMIT();
        if (CVTA) compute_stage<true >(As[i % 3], Bs[i % 3], acc, g, tg, wm, wn);
        else      compute_stage<false>(As[i % 3], Bs[i % 3], acc, g, tg, wm, wn);
    }

#pragma unroll
    for (int mt = 0; mt < 4; mt++)
#pragma unroll
        for (int nt = 0; nt < 4; nt++) {
            int col = n0 + wn * 32 + nt * 8 + 2 * tg;
#pragma unroll
            for (int rr = 0; rr < 2; rr++) {
                int R = m0 + wm * 64 + mt * 16 + g + rr * 8;
                float v0 = acc[mt][nt][2 * rr + 0];
                float v1 = acc[mt][nt][2 * rr + 1];
                if (MODE == 0) {
                    if (z == 0) {
                        float2 bi = *(const float2*)(bias0 + col);
                        *(float2*)&C0[(size_t)R * P_ + col] =
                            make_float2(v0 + bi.x, v1 + bi.y);
                    } else if (z == 1) {
                        float2 bi = *(const float2*)(bias1 + col);
                        *(float2*)&C1[(size_t)R * P_ + col] =
                            make_float2(v0 + bi.x, v1 + bi.y);
                    } else {
                        int h = z - 2;
                        float2 bi = *(const float2*)(bias2 + h * P_ + col);
                        int b = R >> 8, m = R & 255;
                        *(float2*)&C2[(((size_t)(b * H_ + h)) * M_ + m) * P_ + col] =
                            make_float2(rtf(v0 + bi.x), rtf(v1 + bi.y));
                    }
                } else if (MODE == 1) {
                    if (z == 0) {
                        float2 bi = *(const float2*)(bias0 + col);
                        *(float2*)&C0[(size_t)R * P_ + col] =
                            make_float2(rtf(v0 + bi.x), rtf(v1 + bi.y));
                    } else {
                        float2 bi = *(const float2*)(bias1 + col);
                        int b = R >> 11, s = R & 2047;
                        C1[((size_t)b * P_ + col) * S_ + s]     = rtf(v0 + bi.x);
                        C1[((size_t)b * P_ + col + 1) * S_ + s] = rtf(v1 + bi.y);
                    }
                } else if (MODE == 2) {
                    *(float2*)&C0[((size_t)z * M_ + R) * S_ + col] =
                        make_float2(v0 * SCALE, v1 * SCALE);
                } else if (MODE == 3) {
                    int b = z >> 3, h = z & 7;
                    float sw = selfw[(size_t)z * M_ + R];
                    float2 mvv = *(const float2*)(mvp + ((size_t)(b * M_ + R)) * P_ + col);
                    *(float2*)&C0[(size_t)(b * M_ + R) * (H_ * P_) + h * P_ + col] =
                        make_float2(rtf(v0 + sw * mvv.x), rtf(v1 + sw * mvv.y));
                } else {
                    float2 bi = *(const float2*)(bias0 + col);
                    *(float2*)&C0[(size_t)R * P_ + col] =
                        make_float2(v0 + bi.x, v1 + bi.y);
                }
            }
        }
}

// ---------------- self score -> g_self ---------------------------------------
__global__ __launch_bounds__(256) void self_score(
    const float* __restrict__ q, const float* __restrict__ mk,
    float* __restrict__ selfo)
{
    int gw = (blockIdx.x * 256 + threadIdx.x) >> 5;
    int lane = threadIdx.x & 31;
    int z = gw >> 8, m = gw & 255, b = z >> 3;
    const float* qp = q + ((size_t)z * M_ + m) * P_;
    const float* kp = mk + ((size_t)b * M_ + m) * P_;
    float s = 0.f;
    for (int i = lane * 4; i < P_; i += 128) {
        float4 qa = *(const float4*)(qp + i);
        float4 ka = *(const float4*)(kp + i);
        s += qa.x * ka.x + qa.y * ka.y + qa.z * ka.z + qa.w * ka.w;
    }
    for (int o = 16; o; o >>= 1) s += __shfl_xor_sync(0xffffffffu, s, o);
    if (lane == 0) selfo[(size_t)z * M_ + m] = s * SCALE;
}

// ---------------- softmax over [self, 2048 probs]; writes rounded probs -----
__global__ __launch_bounds__(256) void softmax_rows(
    float* __restrict__ probs, float* __restrict__ selfv)
{
    float* p = probs + (size_t)blockIdx.x * S_;
    const int tid = threadIdx.x;
    const int lane = tid & 31, wid = tid >> 5;
    __shared__ float red[8];
    float sv = selfv[blockIdx.x];
    float v[8];
    float vmax = sv;
#pragma unroll
    for (int i = 0; i < 8; i++) { v[i] = p[tid + i * 256]; vmax = fmaxf(vmax, v[i]); }
    for (int o = 16; o; o >>= 1) vmax = fmaxf(vmax, __shfl_xor_sync(0xffffffffu, vmax, o));
    if (lane == 0) red[wid] = vmax;
    __syncthreads();
    if (tid == 0) {
        float t = red[0];
        for (int i = 1; i < 8; i++) t = fmaxf(t, red[i]);
        red[0] = t;
    }
    __syncthreads();
    vmax = red[0];
    float s = 0.f;
#pragma unroll
    for (int i = 0; i < 8; i++) { v[i] = __expf(v[i] - vmax); s += v[i]; }
    float es = __expf(sv - vmax);
    if (tid == 0) s += es;
    for (int o = 16; o; o >>= 1) s += __shfl_xor_sync(0xffffffffu, s, o);
    if (lane == 0) red[wid] = s;
    __syncthreads();
    if (tid == 0) {
        float t = 0.f;
        for (int i = 0; i < 8; i++) t += red[i];
        red[0] = t;
    }
    __syncthreads();
    float inv = 1.0f / red[0];
#pragma unroll
    for (int i = 0; i < 8; i++) p[tid + i * 256] = rtf(v[i] * inv);
    if (tid == 0) selfv[blockIdx.x] = es * inv;
}

// ---------------- launch ----------------------------------------------------
extern "C" void kernel_launch(void* const* d_in, const int* in_sizes, int n_in,
                              void* d_out, int out_size)
{
    const float* input_seq    = (const float*)d_in[0];
    const float* memory_cells = (const float*)d_in[1];
    const float* Wk = (const float*)d_in[2];
    const float* bk = (const float*)d_in[3];
    const float* Wv = (const float*)d_in[4];
    const float* bv = (const float*)d_in[5];
    const float* Wq = (const float*)d_in[6];
    const float* bq = (const float*)d_in[7];
    const float* Wo = (const float*)d_in[8];
    const float* bo = (const float*)d_in[9];
    float* out = (float*)d_out;

    float *p_ik, *p_ivT, *p_mk, *p_mv, *p_q, *p_pr, *p_sf, *p_cc;
    float *p_WkT, *p_WvT, *p_WqT, *p_WoT;
    cudaGetSymbolAddress((void**)&p_ik,  g_ik);
    cudaGetSymbolAddress((void**)&p_ivT, g_ivT);
    cudaGetSymbolAddress((void**)&p_mk,  g_mk);
    cudaGetSymbolAddress((void**)&p_mv,  g_mv);
    cudaGetSymbolAddress((void**)&p_q,   g_q);
    cudaGetSymbolAddress((void**)&p_pr,  g_probs);
    cudaGetSymbolAddress((void**)&p_sf,  g_self);
    cudaGetSymbolAddress((void**)&p_cc,  g_concat);
    cudaGetSymbolAddress((void**)&p_WkT, g_WkT);
    cudaGetSymbolAddress((void**)&p_WvT, g_WvT);
    cudaGetSymbolAddress((void**)&p_WqT, g_WqT);
    cudaGetSymbolAddress((void**)&p_WoT, g_WoT);

    dim3 tb(32, 8);
    k_transpose<<<dim3(16, 16), tb>>>(Wk, p_WkT, D_, P_);
    k_transpose<<<dim3(16, 16), tb>>>(Wv, p_WvT, D_, P_);
    k_transpose<<<dim3(16, 16, H_), tb>>>(Wq, p_WqT, D_, P_);
    k_transpose<<<dim3(16, 128), tb>>>(Wo, p_WoT, H_ * P_, P_);

    // mem-side: mk, mv, q (fused)
    gemm_nt<0, D_><<<dim3(4, 16, 10), 256>>>(memory_cells, p_WkT, p_WvT, p_WqT,
                                             bk, bv, bq, p_mk, p_mv, p_q,
                                             nullptr, nullptr);
    // input-side: ik, ivT (fused)
    gemm_nt<1, D_><<<dim3(4, 128, 2), 256>>>(input_seq, p_WkT, p_WvT, nullptr,
                                             bk, bv, nullptr, p_ik, p_ivT, nullptr,
                                             nullptr, nullptr);
    // scores
    gemm_nt<2, P_><<<dim3(16, 2, 64), 256>>>(p_q, p_ik, nullptr, nullptr,
                                             nullptr, nullptr, nullptr,
                                             p_pr, nullptr, nullptr,
                                             nullptr, nullptr);
    self_score<<<2048, 256>>>(p_q, p_mk, p_sf);
    softmax_rows<<<B_ * H_ * M_, 256>>>(p_pr, p_sf);
    // attn @ V  (+ self path)
    gemm_nt<3, S_><<<dim3(4, 2, 64), 256>>>(p_pr, p_ivT, nullptr, nullptr,
                                            nullptr, nullptr, nullptr,
                                            p_cc, nullptr, nullptr,
                                            p_sf, p_mv);
    // output projection
    gemm_nt<4, H_ * P_><<<dim3(4, 16, 1), 256>>>(p_cc, p_WoT, nullptr, nullptr,
                                                 bo, nullptr, nullptr,
                                                 out, nullptr, nullptr,
                                                 nullptr, nullptr);
}